// round 16
// baseline (speedup 1.0000x reference)
#include <cuda_runtime.h>
#include <cuda_bf16.h>
#include <cuda_fp16.h>
#include <cuda_fp8.h>
#include <cstdint>

#define BB 64
#define TT 512
#define SS 4
#define HH 512
#define VV 10000
#define HALFH 256

// ---------------- device scratch ----------------
__device__ float g_lse[SS * HH];
__device__ float g_leT[(size_t)SS * VV * HH];          // [s][v][h]
__device__ float g_E[(size_t)BB * TT * HH];            // exp(em - smax)
__device__ float g_smax[BB * TT];
__device__ unsigned char g_P8[HH * HH];                // e5m2(P), row-major [j][k]
__device__ float g_corr[HH];                           // per-row quant row-sum correction
__device__ int g_is64;

// ---------------- helpers ----------------
__device__ __forceinline__ float warp_sum(float v) {
    #pragma unroll
    for (int o = 16; o; o >>= 1) v += __shfl_xor_sync(0xffffffffu, v, o);
    return v;
}
__device__ __forceinline__ float warp_max(float v) {
    #pragma unroll
    for (int o = 16; o; o >>= 1) v = fmaxf(v, __shfl_xor_sync(0xffffffffu, v, o));
    return v;
}
__device__ __forceinline__ uint32_t smem_u32(const void* p) {
    uint32_t a;
    asm("{ .reg .u64 t; cvta.to.shared.u64 t, %1; cvt.u32.u64 %0, t; }" : "=r"(a) : "l"(p));
    return a;
}
__device__ __forceinline__ __half2 u32_h2(unsigned u) {
    __half2 h;
    *reinterpret_cast<unsigned*>(&h) = u;
    return h;
}
// e5m2 IS the top byte of fp16: dequant = ONE PRMT per half2 pair, value EXACT.
__device__ __forceinline__ __half2 e5lo(unsigned q) { return u32_h2(__byte_perm(q, 0, 0x2404)); }  // (b0,b2)
__device__ __forceinline__ __half2 e5hi(unsigned q) { return u32_h2(__byte_perm(q, 0, 0x3414)); }  // (b1,b3)

__device__ __forceinline__ void mbar_init(uint32_t m, unsigned cnt) {
    asm volatile("mbarrier.init.shared.b64 [%0], %1;" :: "r"(m), "r"(cnt) : "memory");
}
__device__ __forceinline__ void mbar_arrive_remote(uint32_t m_local, unsigned peer) {
    asm volatile("{\n\t.reg .b32 r;\n\t"
                 "mapa.shared::cluster.u32 r, %0, %1;\n\t"
                 "mbarrier.arrive.release.cluster.shared::cluster.b64 _, [r];\n\t}"
                 :: "r"(m_local), "r"(peer) : "memory");
}
__device__ __forceinline__ void st_remote_f32(uint32_t a_local, unsigned peer, float v) {
    asm volatile("{\n\t.reg .b32 r;\n\t"
                 "mapa.shared::cluster.u32 r, %0, %1;\n\t"
                 "st.shared::cluster.f32 [r], %2;\n\t}"
                 :: "r"(a_local), "r"(peer), "f"(v) : "memory");
}
__device__ __forceinline__ void mbar_wait(uint32_t m, unsigned parity) {
    asm volatile("{\n\t.reg .pred P;\n\t"
                 "WL_%=:\n\t"
                 "mbarrier.try_wait.parity.acquire.cluster.shared::cta.b64 P, [%0], %1, 0x989680;\n\t"
                 "@P bra WD_%=;\n\t"
                 "bra WL_%=;\n\t"
                 "WD_%=:\n\t}"
                 :: "r"(m), "r"(parity) : "memory");
}
#define CLUSTER_SYNC_() do { \
    asm volatile("barrier.cluster.arrive.aligned;" ::: "memory"); \
    asm volatile("barrier.cluster.wait.aligned;" ::: "memory"); } while (0)

// ---------------- launch 1: detect (block 2048) + lse (blocks 0..2047) ----------------
__global__ void prep1_kernel(const float* __restrict__ emis, const int* obs32) {
    if (blockIdx.x == SS * HH) {
        if (threadIdx.x == 0) {
            int f = 1;
            for (int i = 0; i < 128; ++i)
                if (obs32[2 * i + 1] != 0) { f = 0; break; }
            g_is64 = f;
        }
        return;
    }
    int row = blockIdx.x;
    const float4* x4 = (const float4*)(emis + (size_t)row * VV);
    int tid = threadIdx.x;
    __shared__ float sr[256];

    float m = -1e30f;
    for (int i = tid; i < VV / 4; i += 256) {
        float4 v = x4[i];
        m = fmaxf(m, fmaxf(fmaxf(v.x, v.y), fmaxf(v.z, v.w)));
    }
    sr[tid] = m; __syncthreads();
    for (int s = 128; s; s >>= 1) { if (tid < s) sr[tid] = fmaxf(sr[tid], sr[tid + s]); __syncthreads(); }
    m = sr[0]; __syncthreads();

    float sum = 0.f;
    for (int i = tid; i < VV / 4; i += 256) {
        float4 v = x4[i];
        sum += expf(v.x - m) + expf(v.y - m) + expf(v.z - m) + expf(v.w - m);
    }
    sr[tid] = sum; __syncthreads();
    for (int s = 128; s; s >>= 1) { if (tid < s) sr[tid] += sr[tid + s]; __syncthreads(); }
    if (tid == 0) g_lse[row] = m + logf(sr[0]);
}

// ---------------- launch 2: transpose (y<16) + psoftmax (y==16, z==0) ----------------
__global__ void prep2_kernel(const float* __restrict__ emis, const float* __restrict__ tran) {
    if (blockIdx.y == 16) {
        if (blockIdx.z != 0) return;
        int j = blockIdx.x;
        const float* row = tran + (size_t)j * HH;
        int tid = threadIdx.y * 32 + threadIdx.x;
        __shared__ float sr[256];

        float a = row[tid], b = row[tid + 256];
        sr[tid] = fmaxf(a, b); __syncthreads();
        for (int s = 128; s; s >>= 1) { if (tid < s) sr[tid] = fmaxf(sr[tid], sr[tid + s]); __syncthreads(); }
        float m = sr[0]; __syncthreads();

        float ea = expf(a - m), eb = expf(b - m);
        sr[tid] = ea + eb; __syncthreads();
        for (int s = 128; s; s >>= 1) { if (tid < s) sr[tid] += sr[tid + s]; __syncthreads(); }
        float inv = 1.0f / sr[0];
        __syncthreads();

        __nv_fp8_storage_t qa = __nv_cvt_float_to_fp8(ea * inv, __NV_SATFINITE, __NV_E5M2);
        __nv_fp8_storage_t qb = __nv_cvt_float_to_fp8(eb * inv, __NV_SATFINITE, __NV_E5M2);
        g_P8[(size_t)j * HH + tid]       = qa;
        g_P8[(size_t)j * HH + tid + 256] = qb;

        __half_raw ha = __nv_cvt_fp8_to_halfraw(qa, __NV_E5M2);
        __half_raw hb = __nv_cvt_fp8_to_halfraw(qb, __NV_E5M2);
        float da = __half2float(*(__half*)&ha) + __half2float(*(__half*)&hb);
        sr[tid] = da; __syncthreads();
        for (int s = 128; s; s >>= 1) { if (tid < s) sr[tid] += sr[tid + s]; __syncthreads(); }
        if (tid == 0) g_corr[j] = 1.0f / sr[0];
        return;
    }

    if (blockIdx.x >= (VV + 31) / 32) return;
    __shared__ float tile[32][33];
    int s  = blockIdx.z;
    int v0 = blockIdx.x * 32;
    int h0 = blockIdx.y * 32;
    int tx = threadIdx.x, ty = threadIdx.y;

    #pragma unroll
    for (int r = 0; r < 4; ++r) {
        int h = h0 + ty + 8 * r;
        int v = v0 + tx;
        float val = 0.f;
        if (v < VV) val = emis[((size_t)s * HH + h) * VV + v] - g_lse[s * HH + h];
        tile[ty + 8 * r][tx] = val;
    }
    __syncthreads();
    #pragma unroll
    for (int r = 0; r < 4; ++r) {
        int v = v0 + ty + 8 * r;
        int h = h0 + tx;
        if (v < VV) g_leT[((size_t)s * VV + v) * HH + h] = tile[tx][ty + 8 * r];
    }
}

// ---------------- launch 3: gather em, smax & E ----------------
__global__ void emE_kernel(const void* __restrict__ obs_raw,
                           const float* __restrict__ priors) {
    int t = blockIdx.x, b = blockIdx.y;
    int tid = threadIdx.x;
    int lane = tid & 31, wid = tid >> 5;
    __shared__ float sm[4];

    int o[SS];
    if (g_is64) {
        const long long* p = (const long long*)obs_raw + ((size_t)(b * TT + t)) * SS;
        #pragma unroll
        for (int s = 0; s < SS; ++s) o[s] = (int)p[s];
    } else {
        const int* p = (const int*)obs_raw + ((size_t)(b * TT + t)) * SS;
        #pragma unroll
        for (int s = 0; s < SS; ++s) o[s] = p[s];
    }

    float4 acc = make_float4(0.f, 0.f, 0.f, 0.f);
    #pragma unroll
    for (int s = 0; s < SS; ++s) {
        const float4* r = (const float4*)(g_leT + ((size_t)s * VV + o[s]) * HH);
        float4 v = r[tid];
        acc.x += v.x; acc.y += v.y; acc.z += v.z; acc.w += v.w;
    }
    acc.x *= 0.25f; acc.y *= 0.25f; acc.z *= 0.25f; acc.w *= 0.25f;

    if (t == 0) {
        float4 pr = ((const float4*)priors)[tid];
        acc.x += pr.x; acc.y += pr.y; acc.z += pr.z; acc.w += pr.w;
    }

    float m = fmaxf(fmaxf(acc.x, acc.y), fmaxf(acc.z, acc.w));
    m = warp_max(m);
    if (lane == 0) sm[wid] = m;
    __syncthreads();
    m = fmaxf(fmaxf(sm[0], sm[1]), fmaxf(sm[2], sm[3]));

    float4 e;
    e.x = __expf(acc.x - m); e.y = __expf(acc.y - m);
    e.z = __expf(acc.z - m); e.w = __expf(acc.w - m);
    ((float4*)(g_E + ((size_t)(b * TT + t)) * HH))[tid] = e;
    if (tid == 0) g_smax[b * TT + t] = m;
}

// ---------------- matvec core: 20 smem rows (fp8+PRMT) + 12 register fp16 rows ----------
__device__ __forceinline__ void matvec_half(
    const uint2* __restrict__ P2, const __half2 (*Ph)[4],
    const uint4* __restrict__ ph4, float* __restrict__ prow) {
    __half2 a0 = __float2half2_rn(0.f), a1 = a0, a2 = a0, a3 = a0;
    {
        unsigned prs[16];
        #pragma unroll
        for (int r = 0; r < 4; ++r) *(uint4*)&prs[4 * r] = ph4[r];
        #pragma unroll
        for (int jj = 0; jj < 16; ++jj) {
            uint2 q = P2[(size_t)jj * 64];
            __half2 hp = u32_h2(prs[jj]);
            a0 = __hfma2(hp, e5lo(q.x), a0);
            a1 = __hfma2(hp, e5hi(q.x), a1);
            a2 = __hfma2(hp, e5lo(q.y), a2);
            a3 = __hfma2(hp, e5hi(q.y), a3);
        }
    }
    {
        unsigned prs[16];
        #pragma unroll
        for (int r = 0; r < 4; ++r) *(uint4*)&prs[4 * r] = ph4[4 + r];
        #pragma unroll
        for (int jj = 0; jj < 4; ++jj) {
            uint2 q = P2[(size_t)(16 + jj) * 64];
            __half2 hp = u32_h2(prs[jj]);
            a0 = __hfma2(hp, e5lo(q.x), a0);
            a1 = __hfma2(hp, e5hi(q.x), a1);
            a2 = __hfma2(hp, e5lo(q.y), a2);
            a3 = __hfma2(hp, e5hi(q.y), a3);
        }
        #pragma unroll
        for (int r = 0; r < 12; ++r) {
            __half2 hp = u32_h2(prs[4 + r]);
            a0 = __hfma2(hp, Ph[r][0], a0);
            a1 = __hfma2(hp, Ph[r][1], a1);
            a2 = __hfma2(hp, Ph[r][2], a2);
            a3 = __hfma2(hp, Ph[r][3], a3);
        }
    }
    float2 f0 = __half22float2(a0), f1 = __half22float2(a1);
    float2 f2 = __half22float2(a2), f3 = __half22float2(a3);
    *(float4*)prow       = make_float4(f0.x, f1.x, f0.y, f1.y);
    *(float4*)(prow + 4) = make_float4(f2.x, f3.x, f2.y, f3.y);
}

// ---------------- launch 4: forward, DUAL-batch per cluster ----------------
// Each 2-CTA cluster runs batches 2c and 2c+1 interleaved through the verified
// R15 step machinery; P (smem + register rows) and barriers shared.
// smem layout (bytes)
#define SM_P      0            // 256 rows x 512 e5m2 = 131072
#define SM_PARTA  131072       // 8 x 512 f32 = 16384
#define SM_PARTB  147456       // 16384
#define SM_PHA    163840       // 256 u32 = 1024
#define SM_PHB    164864       // 1024
#define SM_RECVA  165888       // 2 x 256 f32 = 2048
#define SM_RECVB  167936       // 2048
#define SM_REDA   169984       // 8 f32
#define SM_REDB   170016       // 8 f32
#define SM_HPA    170048       // 2 f32
#define SM_HPB    170056       // 2 f32
#define SM_HPFA   170064       // 1 f32
#define SM_HPFB   170068       // 1 f32
#define SM_MBARVA 170072       // 8B (9 arrivals)
#define SM_MBARVB 170080       // 8B
#define SM_MBARFA 170088       // 8B (1 arrival)
#define SM_MBARFB 170096       // 8B
#define SMEM_TOTAL 170112

__global__ void __launch_bounds__(512, 1) __cluster_dims__(2, 1, 1)
forward_kernel(const void* __restrict__ lengths_raw, float* __restrict__ out) {
    extern __shared__ char sm[];
    const int tid  = threadIdx.x;
    const int b0   = (blockIdx.x >> 1) * 2;          // batches b0, b0+1
    const unsigned rank = blockIdx.x & 1;
    const unsigned peer = rank ^ 1;
    const int lane = tid & 31, wid = tid >> 5;
    const bool own = ((unsigned)(tid >> 8) == rank);
    const bool leader = (tid == (int)(rank << 8));
    const int u = tid & 255;

    const uint32_t sbase = smem_u32(sm);
    const uint32_t mbarVA = sbase + SM_MBARVA, mbarVB = sbase + SM_MBARVB;
    const uint32_t mbarFA = sbase + SM_MBARFA, mbarFB = sbase + SM_MBARFB;
    float*    partA = (float*)(sm + SM_PARTA);
    float*    partB = (float*)(sm + SM_PARTB);
    unsigned* p_hA  = (unsigned*)(sm + SM_PHA);
    unsigned* p_hB  = (unsigned*)(sm + SM_PHB);
    float*    recvA = (float*)(sm + SM_RECVA);
    float*    recvB = (float*)(sm + SM_RECVB);
    float*    redA  = (float*)(sm + SM_REDA);
    float*    redB  = (float*)(sm + SM_REDB);
    float*    hpsA  = (float*)(sm + SM_HPA);
    float*    hpsB  = (float*)(sm + SM_HPB);
    float*    hpfA  = (float*)(sm + SM_HPFA);
    float*    hpfB  = (float*)(sm + SM_HPFB);

    if (tid == 0) {
        mbar_init(mbarVA, 9); mbar_init(mbarVB, 9);
        mbar_init(mbarFA, 1); mbar_init(mbarFB, 1);
    }

    // load own j-rows of P (shared by both batches)
    {
        const uint4* src = (const uint4*)(g_P8 + (size_t)rank * HALFH * HH);
        uint4* dst = (uint4*)(sm + SM_P);
        #pragma unroll
        for (int r = 0; r < 16; ++r) dst[tid + 512 * r] = src[tid + 512 * r];
    }
    const float corrk = g_corr[tid];
    __syncthreads();
    CLUSTER_SYNC_();

    // matvec mapping: 8 groups x 64 threads; group g -> own-local j rows [g*32, g*32+32);
    // thread i owns global k = 8i..8i+7.
    const int g = tid >> 6, i = tid & 63;
    const uint2* P2   = (const uint2*)(sm + SM_P) + (size_t)(g * 32) * 64 + i;
    const uint4* ph4A = (const uint4*)(sm + SM_PHA) + g * 8;
    const uint4* ph4B = (const uint4*)(sm + SM_PHB) + g * 8;
    float* prowA = partA + g * 512 + i * 8;
    float* prowB = partB + g * 512 + i * 8;

    // register-resident rows 20..31, pre-dequantized fp16 (48 regs), shared A/B
    __half2 Ph[12][4];
    #pragma unroll
    for (int r = 0; r < 12; ++r) {
        uint2 q = P2[(size_t)(20 + r) * 64];
        Ph[r][0] = e5lo(q.x);
        Ph[r][1] = e5hi(q.x);
        Ph[r][2] = e5lo(q.y);
        Ph[r][3] = e5hi(q.y);
    }

    int lenA, lenB;
    if (g_is64) {
        lenA = (int)((const long long*)lengths_raw)[b0];
        lenB = (int)((const long long*)lengths_raw)[b0 + 1];
    } else {
        lenA = ((const int*)lengths_raw)[b0];
        lenB = ((const int*)lengths_raw)[b0 + 1];
    }
    const int T = lenA > lenB ? lenA : lenB;
    const float* EbA  = g_E + (size_t)b0 * TT * HH;
    const float* EbB  = g_E + (size_t)(b0 + 1) * TT * HH;
    const float* smxA = g_smax + (size_t)b0 * TT;
    const float* smxB = g_smax + (size_t)(b0 + 1) * TT;

    unsigned ppA = 0, ppB = 0;
    float cA = 0.f, runA = 0.f, RA = 1.f, HoA = 1.f;
    float cB = 0.f, runB = 0.f, RB = 1.f, HoB = 1.f;

    float eA = own ? __ldg(EbA + tid) : 0.f;
    float eB = own ? __ldg(EbB + tid) : 0.f;
    float smtA = leader ? __ldg(smxA) : 0.f;
    float smtB = leader ? __ldg(smxB) : 0.f;

    for (int t = 0; t < T; ++t) {
        const int bufW = t & 1, bufR = bufW ^ 1;
        const bool actA = t < lenA, actB = t < lenB;

        float eA_n = 0.f, eB_n = 0.f, smtA_n = 0.f, smtB_n = 0.f;
        if (own) {
            if (t + 1 < lenA) eA_n = __ldg(EbA + (size_t)(t + 1) * HH + tid);
            if (t + 1 < lenB) eB_n = __ldg(EbB + (size_t)(t + 1) * HH + tid);
        }
        if (leader) {
            if (t + 1 < lenA) smtA_n = __ldg(smxA + t + 1);
            if (t + 1 < lenB) smtB_n = __ldg(smxB + t + 1);
        }

        float wA = 0.f, wB = 0.f;
        if (t == 0) {
            if (own) { wA = eA; wB = eB; }
        } else {
            if (actA) matvec_half(P2, Ph, ph4A, prowA);
            if (actB) matvec_half(P2, Ph, ph4B, prowB);
            __syncthreads();

            if (actA) {
                float tot = 0.f;
                #pragma unroll
                for (int r = 0; r < 8; ++r) tot += partA[r * 512 + tid];
                if (!own) {
                    st_remote_f32(sbase + SM_RECVA + ((unsigned)bufW << 10) + 4u * (unsigned)u, peer, tot);
                    __syncwarp();
                    if (lane == 0) mbar_arrive_remote(mbarVA, peer);
                } else {
                    mbar_wait(mbarVA, ppA); ppA ^= 1;
                    float Hp = hpsA[bufR];
                    RA = RA * Hp * __frcp_rn(HoA);
                    wA = eA * fmaf(RA, recvA[bufW * 256 + u], tot);
                }
            }
            if (actB) {
                float tot = 0.f;
                #pragma unroll
                for (int r = 0; r < 8; ++r) tot += partB[r * 512 + tid];
                if (!own) {
                    st_remote_f32(sbase + SM_RECVB + ((unsigned)bufW << 10) + 4u * (unsigned)u, peer, tot);
                    __syncwarp();
                    if (lane == 0) mbar_arrive_remote(mbarVB, peer);
                } else {
                    mbar_wait(mbarVB, ppB); ppB ^= 1;
                    float Hp = hpsB[bufR];
                    RB = RB * Hp * __frcp_rn(HoB);
                    wB = eB * fmaf(RB, recvB[bufW * 256 + u], tot);
                }
            }
        }

        if (own) {
            if (actA) { float s1 = warp_sum(wA); if (lane == 0) redA[wid & 7] = s1; }
            if (actB) { float s1 = warp_sum(wB); if (lane == 0) redB[wid & 7] = s1; }
            asm volatile("bar.sync 1, 256;" ::: "memory");

            if (actA) {
                float Hn = redA[0] + redA[1] + redA[2] + redA[3] + redA[4] + redA[5] + redA[6] + redA[7];
                float pk = wA * __frcp_rn(Hn + Hn) * corrk;
                unsigned hu = (unsigned)__half_as_ushort(__float2half_rn(pk));
                p_hA[u] = hu | (hu << 16);
                HoA = Hn;
                if (leader) {
                    if (t < lenA - 1) {
                        st_remote_f32(sbase + SM_HPA + 4u * (unsigned)bufW, peer, HoA);
                        mbar_arrive_remote(mbarVA, peer);
                    } else {
                        st_remote_f32(sbase + SM_HPFA, peer, HoA);
                        mbar_arrive_remote(mbarFA, peer);
                    }
                    cA += smtA;
                    runA += __logf(HoA + HoA);
                }
            }
            if (actB) {
                float Hn = redB[0] + redB[1] + redB[2] + redB[3] + redB[4] + redB[5] + redB[6] + redB[7];
                float pk = wB * __frcp_rn(Hn + Hn) * corrk;
                unsigned hu = (unsigned)__half_as_ushort(__float2half_rn(pk));
                p_hB[u] = hu | (hu << 16);
                HoB = Hn;
                if (leader) {
                    if (t < lenB - 1) {
                        st_remote_f32(sbase + SM_HPB + 4u * (unsigned)bufW, peer, HoB);
                        mbar_arrive_remote(mbarVB, peer);
                    } else {
                        st_remote_f32(sbase + SM_HPFB, peer, HoB);
                        mbar_arrive_remote(mbarFB, peer);
                    }
                    cB += smtB;
                    runB += __logf(HoB + HoB);
                }
            }
        }
        eA = eA_n; eB = eB_n; smtA = smtA_n; smtB = smtB_n;
        __syncthreads();
    }

    if (leader && rank == 0) {
        mbar_wait(mbarFA, 0);
        out[b0] = cA + runA - __logf(HoA + HoA) + __logf(fmaf(RA, hpfA[0], HoA));
        mbar_wait(mbarFB, 0);
        out[b0 + 1] = cB + runB - __logf(HoB + HoB) + __logf(fmaf(RB, hpfB[0], HoB));
    }
    CLUSTER_SYNC_();
}

// ---------------- launcher (4 launches; forward on ncu capture slot) ----------
extern "C" void kernel_launch(void* const* d_in, const int* in_sizes, int n_in,
                              void* d_out, int out_size) {
    const void*  obs     = d_in[0];
    const void*  lengths = d_in[1];
    const float* emis    = (const float*)d_in[2];
    const float* tran    = (const float*)d_in[3];
    const float* priors  = (const float*)d_in[4];
    float* out = (float*)d_out;

    cudaFuncSetAttribute(forward_kernel, cudaFuncAttributeMaxDynamicSharedMemorySize, SMEM_TOTAL);

    prep1_kernel<<<SS * HH + 1, 256>>>(emis, (const int*)obs);
    prep2_kernel<<<dim3(512, 17, 4), dim3(32, 8)>>>(emis, tran);
    emE_kernel<<<dim3(TT, BB), 128>>>(obs, priors);
    forward_kernel<<<BB, 512, SMEM_TOTAL>>>(lengths, out);
}

// round 17
// speedup vs baseline: 1.1794x; 1.1794x over previous
#include <cuda_runtime.h>
#include <cuda_bf16.h>
#include <cuda_fp16.h>
#include <cuda_fp8.h>
#include <cstdint>

#define BB 64
#define TT 512
#define SS 4
#define HH 512
#define VV 10000
#define HALFH 256

// ---------------- device scratch ----------------
__device__ float g_lse[SS * HH];
__device__ float g_leT[(size_t)SS * VV * HH];          // [s][v][h]
__device__ float g_E[(size_t)BB * TT * HH];            // exp(em - smax)
__device__ float g_smax[BB * TT];
__device__ unsigned char g_P8[HH * HH];                // e5m2(P), row-major [j][k]
__device__ unsigned char g_P8F[2 * 131072];            // chunk-interleaved k-major [r][c][k][16]
__device__ float g_corr[HH];                           // per-row quant row-sum correction
__device__ int g_is64;

// ---------------- helpers ----------------
__device__ __forceinline__ float warp_sum(float v) {
    #pragma unroll
    for (int o = 16; o; o >>= 1) v += __shfl_xor_sync(0xffffffffu, v, o);
    return v;
}
__device__ __forceinline__ float warp_max(float v) {
    #pragma unroll
    for (int o = 16; o; o >>= 1) v = fmaxf(v, __shfl_xor_sync(0xffffffffu, v, o));
    return v;
}
__device__ __forceinline__ uint32_t smem_u32(const void* p) {
    uint32_t a;
    asm("{ .reg .u64 t; cvta.to.shared.u64 t, %1; cvt.u32.u64 %0, t; }" : "=r"(a) : "l"(p));
    return a;
}
__device__ __forceinline__ __half2 u32_h2(unsigned u) {
    __half2 h;
    *reinterpret_cast<unsigned*>(&h) = u;
    return h;
}
// e5m2 IS the top byte of fp16: dequant = ONE PRMT per half2 pair, value EXACT.
__device__ __forceinline__ __half2 e5lo(unsigned q) { return u32_h2(__byte_perm(q, 0, 0x2404)); }  // (b0,b2)
__device__ __forceinline__ __half2 e5hi(unsigned q) { return u32_h2(__byte_perm(q, 0, 0x3414)); }  // (b1,b3)

__device__ __forceinline__ void mbar_init(uint32_t m, unsigned cnt) {
    asm volatile("mbarrier.init.shared.b64 [%0], %1;" :: "r"(m), "r"(cnt) : "memory");
}
__device__ __forceinline__ void mbar_arrive_remote(uint32_t m_local, unsigned peer) {
    asm volatile("{\n\t.reg .b32 r;\n\t"
                 "mapa.shared::cluster.u32 r, %0, %1;\n\t"
                 "mbarrier.arrive.release.cluster.shared::cluster.b64 _, [r];\n\t}"
                 :: "r"(m_local), "r"(peer) : "memory");
}
__device__ __forceinline__ void st_remote_f32(uint32_t a_local, unsigned peer, float v) {
    asm volatile("{\n\t.reg .b32 r;\n\t"
                 "mapa.shared::cluster.u32 r, %0, %1;\n\t"
                 "st.shared::cluster.f32 [r], %2;\n\t}"
                 :: "r"(a_local), "r"(peer), "f"(v) : "memory");
}
__device__ __forceinline__ void mbar_wait(uint32_t m, unsigned parity) {
    asm volatile("{\n\t.reg .pred P;\n\t"
                 "WL_%=:\n\t"
                 "mbarrier.try_wait.parity.acquire.cluster.shared::cta.b64 P, [%0], %1, 0x989680;\n\t"
                 "@P bra WD_%=;\n\t"
                 "bra WL_%=;\n\t"
                 "WD_%=:\n\t}"
                 :: "r"(m), "r"(parity) : "memory");
}
#define CLUSTER_SYNC_() do { \
    asm volatile("barrier.cluster.arrive.aligned;" ::: "memory"); \
    asm volatile("barrier.cluster.wait.aligned;" ::: "memory"); } while (0)

// ---------------- launch 1: lse (0..2047) + detect (2048) + psoftmax (2049..2560) ----
__global__ void prep1_kernel(const float* __restrict__ emis,
                             const float* __restrict__ tran,
                             const int* obs32) {
    if (blockIdx.x == SS * HH) {
        if (threadIdx.x == 0) {
            int f = 1;
            for (int i = 0; i < 128; ++i)
                if (obs32[2 * i + 1] != 0) { f = 0; break; }
            g_is64 = f;
        }
        return;
    }
    if (blockIdx.x > SS * HH) {
        // psoftmax for row j; e5m2 unscaled + row-sum corr
        int j = blockIdx.x - (SS * HH + 1);
        const float* row = tran + (size_t)j * HH;
        int tid = threadIdx.x;
        __shared__ float sr[256];

        float a = row[tid], b = row[tid + 256];
        sr[tid] = fmaxf(a, b); __syncthreads();
        for (int s = 128; s; s >>= 1) { if (tid < s) sr[tid] = fmaxf(sr[tid], sr[tid + s]); __syncthreads(); }
        float m = sr[0]; __syncthreads();

        float ea = expf(a - m), eb = expf(b - m);
        sr[tid] = ea + eb; __syncthreads();
        for (int s = 128; s; s >>= 1) { if (tid < s) sr[tid] += sr[tid + s]; __syncthreads(); }
        float inv = 1.0f / sr[0];
        __syncthreads();

        __nv_fp8_storage_t qa = __nv_cvt_float_to_fp8(ea * inv, __NV_SATFINITE, __NV_E5M2);
        __nv_fp8_storage_t qb = __nv_cvt_float_to_fp8(eb * inv, __NV_SATFINITE, __NV_E5M2);
        g_P8[(size_t)j * HH + tid]       = qa;
        g_P8[(size_t)j * HH + tid + 256] = qb;

        __half_raw ha = __nv_cvt_fp8_to_halfraw(qa, __NV_E5M2);
        __half_raw hb = __nv_cvt_fp8_to_halfraw(qb, __NV_E5M2);
        float da = __half2float(*(__half*)&ha) + __half2float(*(__half*)&hb);
        sr[tid] = da; __syncthreads();
        for (int s = 128; s; s >>= 1) { if (tid < s) sr[tid] += sr[tid + s]; __syncthreads(); }
        if (tid == 0) g_corr[j] = 1.0f / sr[0];
        return;
    }
    // lse over V
    int row = blockIdx.x;
    const float4* x4 = (const float4*)(emis + (size_t)row * VV);
    int tid = threadIdx.x;
    __shared__ float sr[256];

    float m = -1e30f;
    for (int i = tid; i < VV / 4; i += 256) {
        float4 v = x4[i];
        m = fmaxf(m, fmaxf(fmaxf(v.x, v.y), fmaxf(v.z, v.w)));
    }
    sr[tid] = m; __syncthreads();
    for (int s = 128; s; s >>= 1) { if (tid < s) sr[tid] = fmaxf(sr[tid], sr[tid + s]); __syncthreads(); }
    m = sr[0]; __syncthreads();

    float sum = 0.f;
    for (int i = tid; i < VV / 4; i += 256) {
        float4 v = x4[i];
        sum += expf(v.x - m) + expf(v.y - m) + expf(v.z - m) + expf(v.w - m);
    }
    sr[tid] = sum; __syncthreads();
    for (int s = 128; s; s >>= 1) { if (tid < s) sr[tid] += sr[tid + s]; __syncthreads(); }
    if (tid == 0) g_lse[row] = m + logf(sr[0]);
}

// ---------------- launch 2: transpose (y<16) + ptrans repack (y==16, z<2) ----------------
__global__ void prep2_kernel(const float* __restrict__ emis) {
    if (blockIdx.y == 16) {
        // chunk-interleaved k-major repack: g_P8F[r][c*8192 + k*16 + d] = g_P8[r*256+c*16+d][k]
        if (blockIdx.z >= 2 || blockIdx.x >= 16) return;
        __shared__ unsigned char stage[16 * 516];
        int r  = blockIdx.z;
        int cc = blockIdx.x;
        int tid = threadIdx.y * 32 + threadIdx.x;   // 256 threads

        for (int idx = tid; idx < 16 * 512; idx += 256) {
            int d = idx >> 9, kk = idx & 511;
            stage[d * 516 + kk] = g_P8[(size_t)(r * 256 + cc * 16 + d) * 512 + kk];
        }
        __syncthreads();
        for (int idx = tid; idx < 16 * 512; idx += 256) {
            int kk = idx >> 4, d = idx & 15;
            g_P8F[(size_t)r * 131072 + cc * 8192 + idx] = stage[d * 516 + kk];
        }
        return;
    }

    if (blockIdx.x >= (VV + 31) / 32) return;
    __shared__ float tile[32][33];
    int s  = blockIdx.z;
    int v0 = blockIdx.x * 32;
    int h0 = blockIdx.y * 32;
    int tx = threadIdx.x, ty = threadIdx.y;

    #pragma unroll
    for (int r = 0; r < 4; ++r) {
        int h = h0 + ty + 8 * r;
        int v = v0 + tx;
        float val = 0.f;
        if (v < VV) val = emis[((size_t)s * HH + h) * VV + v] - g_lse[s * HH + h];
        tile[ty + 8 * r][tx] = val;
    }
    __syncthreads();
    #pragma unroll
    for (int r = 0; r < 4; ++r) {
        int v = v0 + ty + 8 * r;
        int h = h0 + tx;
        if (v < VV) g_leT[((size_t)s * VV + v) * HH + h] = tile[tx][ty + 8 * r];
    }
}

// ---------------- launch 3: gather em, smax & E ----------------
__global__ void emE_kernel(const void* __restrict__ obs_raw,
                           const float* __restrict__ priors) {
    int t = blockIdx.x, b = blockIdx.y;
    int tid = threadIdx.x;
    int lane = tid & 31, wid = tid >> 5;
    __shared__ float sm[4];

    int o[SS];
    if (g_is64) {
        const long long* p = (const long long*)obs_raw + ((size_t)(b * TT + t)) * SS;
        #pragma unroll
        for (int s = 0; s < SS; ++s) o[s] = (int)p[s];
    } else {
        const int* p = (const int*)obs_raw + ((size_t)(b * TT + t)) * SS;
        #pragma unroll
        for (int s = 0; s < SS; ++s) o[s] = p[s];
    }

    float4 acc = make_float4(0.f, 0.f, 0.f, 0.f);
    #pragma unroll
    for (int s = 0; s < SS; ++s) {
        const float4* r = (const float4*)(g_leT + ((size_t)s * VV + o[s]) * HH);
        float4 v = r[tid];
        acc.x += v.x; acc.y += v.y; acc.z += v.z; acc.w += v.w;
    }
    acc.x *= 0.25f; acc.y *= 0.25f; acc.z *= 0.25f; acc.w *= 0.25f;

    if (t == 0) {
        float4 pr = ((const float4*)priors)[tid];
        acc.x += pr.x; acc.y += pr.y; acc.z += pr.z; acc.w += pr.w;
    }

    float m = fmaxf(fmaxf(acc.x, acc.y), fmaxf(acc.z, acc.w));
    m = warp_max(m);
    if (lane == 0) sm[wid] = m;
    __syncthreads();
    m = fmaxf(fmaxf(sm[0], sm[1]), fmaxf(sm[2], sm[3]));

    float4 e;
    e.x = __expf(acc.x - m); e.y = __expf(acc.y - m);
    e.z = __expf(acc.z - m); e.w = __expf(acc.w - m);
    ((float4*)(g_E + ((size_t)(b * TT + t)) * HH))[tid] = e;
    if (tid == 0) g_smax[b * TT + t] = m;
}

// ---------------- launch 4: forward, ROW-split cluster, k-per-thread reg-P --------------
// Thread k (= tid) holds its ENTIRE P column over own 256 j in 64 registers (fp8).
// tot is thread-local: no part array, no cross-warp reduce, one __syncthreads/step.
// p stored pair-swizzled in smem so PRMT pairs (j0,j2)/(j1,j3) line up (R9-verified).
// smem layout (bytes)
#define SM_PH    0            // 256 halfs (pair-swizzled p, own j's) = 512
#define SM_RECV  512          // 2 x 256 f32 (peer partials, double buffered) = 2048
#define SM_RED   2560         // 8 f32
#define SM_HP    2592         // 2 f32 (peer H, double buffered)
#define SM_HPF   2600         // 1 f32 (peer final H) + pad
#define SM_MBAR  2608         // 8B (9 arrivals: 8 partial-warps + 1 H)
#define SM_MBARF 2616         // 8B (1 arrival: final H)
#define SMEM_TOTAL 2624

__global__ void __launch_bounds__(512, 1) __cluster_dims__(2, 1, 1)
forward_kernel(const void* __restrict__ lengths_raw, float* __restrict__ out) {
    extern __shared__ char sm[];
    const int tid  = threadIdx.x;                       // global k = tid
    const int b    = blockIdx.x >> 1;
    const unsigned rank = blockIdx.x & 1;
    const unsigned peer = rank ^ 1;
    const int lane = tid & 31, wid = tid >> 5;
    const bool own = ((unsigned)(tid >> 8) == rank);    // k in own half (== own state set)
    const bool leader = (tid == (int)(rank << 8));
    const int u = tid & 255;

    const uint32_t sbase = smem_u32(sm);
    const uint32_t mbarV = sbase + SM_MBAR;
    const uint32_t mbarF = sbase + SM_MBARF;
    float* recv = (float*)(sm + SM_RECV);
    float* red  = (float*)(sm + SM_RED);
    float* hps  = (float*)(sm + SM_HP);
    float* hpf  = (float*)(sm + SM_HPF);
    const uint4* ph16 = (const uint4*)(sm + SM_PH);

    if (tid == 0) { mbar_init(mbarV, 9); mbar_init(mbarF, 1); }

    // register-resident P column: 16 chunks x 16 j = 256 j (fp8), for k = tid
    uint4 Pr4[16];
    {
        const uint4* src = (const uint4*)(g_P8F + (size_t)rank * 131072);
        #pragma unroll
        for (int c = 0; c < 16; ++c) Pr4[c] = src[c * 512 + tid];
    }
    const float corrk = g_corr[tid];   // correction for state j = tid (own threads use it)
    __syncthreads();
    CLUSTER_SYNC_();

    const int len = g_is64 ? (int)((const long long*)lengths_raw)[b]
                           : ((const int*)lengths_raw)[b];
    const float* Eb  = g_E + (size_t)b * TT * HH;
    const float* smx = g_smax + (size_t)b * TT;

    unsigned pp = 0;
    float c = 0.f, run = 0.f;
    float R = 1.f;            // cross-half scale ratio (stale by 1 step; stable)
    float Ho = 1.f;           // own half-sum (register, all own threads)

    float e_cur = own ? __ldg(Eb + tid) : 0.f;
    float smt_cur = leader ? __ldg(smx) : 0.f;

    for (int t = 0; t < len; ++t) {
        const int bufW = t & 1, bufR = bufW ^ 1;

        float e_next = 0.f, smt_next = 0.f;
        if (t + 1 < len) {
            if (own) e_next = __ldg(Eb + (size_t)(t + 1) * HH + tid);
            if (leader) smt_next = __ldg(smx + t + 1);
        }

        float w = 0.f;
        if (t == 0) {
            if (own) w = e_cur;
        } else {
            // matvec: thread-local accumulation over all own 256 j for k = tid
            __half2 a0 = __float2half2_rn(0.f), a1 = a0, a2 = a0, a3 = a0;
            #pragma unroll
            for (int ch = 0; ch < 16; ++ch) {
                uint4 q  = Pr4[ch];
                uint4 pa = ph16[2 * ch];
                uint4 pb = ph16[2 * ch + 1];
                a0 = __hfma2(u32_h2(pa.x), e5lo(q.x), a0);
                a1 = __hfma2(u32_h2(pa.y), e5hi(q.x), a1);
                a2 = __hfma2(u32_h2(pa.z), e5lo(q.y), a2);
                a3 = __hfma2(u32_h2(pa.w), e5hi(q.y), a3);
                a0 = __hfma2(u32_h2(pb.x), e5lo(q.z), a0);
                a1 = __hfma2(u32_h2(pb.y), e5hi(q.z), a1);
                a2 = __hfma2(u32_h2(pb.z), e5lo(q.w), a2);
                a3 = __hfma2(u32_h2(pb.w), e5hi(q.w), a3);
            }
            __half2 hs = __hadd2(__hadd2(a0, a1), __hadd2(a2, a3));
            float2 fs = __half22float2(hs);
            float tot = fs.x + fs.y;

            if (!own) {
                // ship peer's k immediately (thread-local; no barrier needed first)
                st_remote_f32(sbase + SM_RECV + ((unsigned)bufW << 10) + 4u * (unsigned)u, peer, tot);
                __syncwarp();
                if (lane == 0) mbar_arrive_remote(mbarV, peer);
            } else {
                // wait: peer partial-warps (this step) + peer H_{t-1}
                mbar_wait(mbarV, pp); pp ^= 1;
                float Hp = hps[bufR];                 // peer H_{t-1}
                R = R * Hp * __frcp_rn(Ho);           // Ho still holds H_{t-1}
                w = e_cur * fmaf(R, recv[bufW * 256 + u], tot);
            }
        }

        if (own) {
            float s1 = warp_sum(w);
            if (lane == 0) red[wid & 7] = s1;
            asm volatile("bar.sync 1, 256;" ::: "memory");
            float Hn = red[0] + red[1] + red[2] + red[3] + red[4] + red[5] + red[6] + red[7];

            // normalize own half by 2*Hn (current -> stable); corr fixes quant row sums
            float pk = w * __frcp_rn(Hn + Hn) * corrk;
            __half hv = __float2half_rn(pk);
            int idx = (u & ~3) | ((u & 1) << 1) | ((u >> 1) & 1);   // pair swizzle (R9)
            ((__half*)(sm + SM_PH))[idx] = hv;
            Ho = Hn;

            if (leader) {
                if (t < len - 1) {
                    st_remote_f32(sbase + SM_HP + 4u * (unsigned)bufW, peer, Ho);
                    mbar_arrive_remote(mbarV, peer);
                } else {
                    st_remote_f32(sbase + SM_HPF, peer, Ho);
                    mbar_arrive_remote(mbarF, peer);
                }
                c += smt_cur;
                run += __logf(Ho + Ho);
            }
        }
        e_cur = e_next; smt_cur = smt_next;
        __syncthreads();
    }

    if (leader && rank == 0) {
        mbar_wait(mbarF, 0);
        // run includes log(2 Ho_L); replace with log(Ho_L + R*Hp_L)
        out[b] = c + run - __logf(Ho + Ho) + __logf(fmaf(R, hpf[0], Ho));
    }
    CLUSTER_SYNC_();
}

// ---------------- launcher (4 launches; forward on ncu capture slot) ----------
extern "C" void kernel_launch(void* const* d_in, const int* in_sizes, int n_in,
                              void* d_out, int out_size) {
    const void*  obs     = d_in[0];
    const void*  lengths = d_in[1];
    const float* emis    = (const float*)d_in[2];
    const float* tran    = (const float*)d_in[3];
    const float* priors  = (const float*)d_in[4];
    float* out = (float*)d_out;

    cudaFuncSetAttribute(forward_kernel, cudaFuncAttributeMaxDynamicSharedMemorySize, SMEM_TOTAL);

    prep1_kernel<<<SS * HH + 1 + HH, 256>>>(emis, tran, (const int*)obs);
    prep2_kernel<<<dim3(512, 17, 4), dim3(32, 8)>>>(emis);
    emE_kernel<<<dim3(TT, BB), 128>>>(obs, priors);
    forward_kernel<<<BB * 2, 512, SMEM_TOTAL>>>(lengths, out);
}